// round 15
// baseline (speedup 1.0000x reference)
#include <cuda_runtime.h>
#include <cuda_bf16.h>
#include <cuda_fp16.h>
#include <math.h>
#include <stdint.h>

#define VV 32000
#define EE 64
#define HH 128
#define SS 1024
#define BB 128
#define TT 64
#define GG 384
#define NT2 16
#define NTILES 2000        // VV / NT2
#define GRID 256

// ---------------- device scratch ----------------
__device__ float g_gi[(size_t)SS*BB*GG];
__device__ float g_eoT[(size_t)BB*SS*HH];     // enc_out [b][s][h] fp32
__device__ __half g_eo16[(size_t)BB*SS*HH];   // enc_out [b][s][h] fp16 (context reads)
__device__ float g_epBS[(size_t)BB*SS*HH];    // enc_proj [b][s][h] fp32
__device__ __half g_epT[(size_t)BB*HH*SS];    // enc_proj [b][h][s] fp16 (score reads)
__device__ __half g_Wh[(size_t)VV*256];       // fp16 high split [v][k]
__device__ __half g_Wm[(size_t)VV*256];       // fp16 residual * 2048
__device__ float2 g_wiT2[192*192];            // [k][jpair] of dec_Wih
__device__ float2 g_whT2[128*192];            // [k][jpair] of dec_Whh
__device__ float g_h[BB*HH];
__device__ float g_ctx[BB*HH];                // ctx for current step
__device__ float g_gh[BB*GG];                 // Whh . h (no bias)
__device__ float g_gic[BB*GG];                // Wih[:,64:] . ctx (no bias)
__device__ uint32_t g_xh[BB*128];             // x fp16x2 high split [b][pair]
__device__ uint32_t g_xm[BB*128];             // x fp16x2 residual*2048
__device__ float g_pval[(size_t)BB*2048];
__device__ int   g_pidx[(size_t)BB*2048];
__device__ int   g_tctr[TT+1];                // per-step tile counters (slot TT = probe)

__device__ __forceinline__ float sig_acc(float x){ return 1.0f/(1.0f + expf(-x)); }
__device__ __forceinline__ float tanh_fast(float x){
  return 1.0f - __fdividef(2.0f, __expf(2.0f*x) + 1.0f);
}

// ---------------- helpers ----------------
__device__ __forceinline__ uint32_t s2u(const void* p){
  uint32_t a;
  asm("{ .reg .u64 t; cvta.to.shared.u64 t, %1; cvt.u32.u64 %0, t; }" : "=r"(a) : "l"(p));
  return a;
}
__device__ __forceinline__ uint32_t pack_h2(__half lo, __half hi){
  __half2 t = __halves2half2(lo, hi);
  return *(uint32_t*)&t;
}
__device__ __forceinline__ void split2h(float2 f, uint32_t& h, uint32_t& m){
  __half h0=__float2half_rn(f.x), h1=__float2half_rn(f.y);
  float r0=(f.x-__half2float(h0))*2048.0f, r1=(f.y-__half2float(h1))*2048.0f;
  h = pack_h2(h0,h1);
  m = pack_h2(__float2half_rn(r0), __float2half_rn(r1));
}
__device__ __forceinline__ void cpasync16(uint32_t saddr, const void* gaddr){
  asm volatile("cp.async.cg.shared.global [%0], [%1], 16;" :: "r"(saddr), "l"(gaddr) : "memory");
}

#define MMA(cc, aa, bb0, bb1) \
  asm volatile("mma.sync.aligned.m16n8k16.row.col.f32.f16.f16.f32 " \
    "{%0,%1,%2,%3}, {%4,%5,%6,%7}, {%8,%9}, {%0,%1,%2,%3};" \
    : "+f"(cc[0]),"+f"(cc[1]),"+f"(cc[2]),"+f"(cc[3]) \
    : "r"(aa[0]),"r"(aa[1]),"r"(aa[2]),"r"(aa[3]), "r"(bb0),"r"(bb1))

#define LDSM4(r0,r1,r2,r3,addr) \
  asm volatile("ldmatrix.sync.aligned.m8n8.x4.shared.b16 {%0,%1,%2,%3}, [%4];" \
    : "=r"(r0),"=r"(r1),"=r"(r2),"=r"(r3) : "r"(addr))

// ---------------- setup: split out_W into 2 fp16 levels ----------------
__global__ void k_wsplit(const float* __restrict__ outW){
  size_t i4 = (size_t)blockIdx.x*256 + threadIdx.x;
  float4 w = ((const float4*)outW)[i4];
  uint2 uh, um;
  split2h(make_float2(w.x,w.y), uh.x, um.x);
  split2h(make_float2(w.z,w.w), uh.y, um.y);
  ((uint2*)g_Wh)[i4] = uh;
  ((uint2*)g_Wm)[i4] = um;
}

// ---------------- setup: transpose decoder GRU weights ----------------
__global__ void k_wtrans(const float* __restrict__ dWih, const float* __restrict__ dWhh){
  int idx = blockIdx.x*256 + threadIdx.x;
  if(idx < 192*192){
    int k = idx/192, j = idx%192;
    g_wiT2[idx] = make_float2(dWih[(size_t)(2*j)*192+k], dWih[(size_t)(2*j+1)*192+k]);
  } else {
    int i2 = idx - 192*192;
    if(i2 < 128*192){
      int k = i2/192, j = i2%192;
      g_whT2[i2] = make_float2(dWhh[(size_t)(2*j)*128+k], dWhh[(size_t)(2*j+1)*128+k]);
    }
  }
}

// ---------------- encoder input projection (also resets tile counters) ----------------
__global__ void __launch_bounds__(384,2) k_giall(const int* __restrict__ seq,
      const float* __restrict__ emb, const float* __restrict__ Wih,
      const float* __restrict__ bih){
  if(blockIdx.x==0 && threadIdx.x < TT+1) g_tctr[threadIdx.x] = GRID;
  int g = threadIdx.x;
  float w[64];
  const float4* wp = (const float4*)(Wih + (size_t)g*64);
  #pragma unroll
  for(int i=0;i<16;i++){ float4 q=wp[i]; w[4*i]=q.x; w[4*i+1]=q.y; w[4*i+2]=q.z; w[4*i+3]=q.w; }
  float bias = bih[g];
  __shared__ float xs[2][64];
  const int ROWS = (SS*BB)/512;
  size_t base = (size_t)blockIdx.x * ROWS;
  if(g<64){ int tok0 = seq[base]; xs[0][g] = emb[(size_t)tok0*EE + g]; }
  __syncthreads();
  for(int r=0;r<ROWS;r++){
    int cur=r&1, nxt=cur^1;
    if(r+1<ROWS && g<64){
      int tok2 = seq[base+r+1];
      xs[nxt][g] = emb[(size_t)tok2*EE + g];
    }
    float a0=0,a1=0,a2=0,a3=0;
    #pragma unroll
    for(int k=0;k<64;k+=4){
      a0 += w[k]*xs[cur][k];     a1 += w[k+1]*xs[cur][k+1];
      a2 += w[k+2]*xs[cur][k+2]; a3 += w[k+3]*xs[cur][k+3];
    }
    g_gi[(base+r)*GG + g] = (a0+a1)+(a2+a3) + bias;
    __syncthreads();
  }
}

// ---------------- encoder recurrence ----------------
__global__ void __launch_bounds__(384,1) k_encrec(const float* __restrict__ Whh,
      const float* __restrict__ bhh){
  extern __shared__ float sm[];
  float* whh_s = sm;
  float* hs    = sm + 12288;
  float* ghs   = hs + 128;
  float* gis   = ghs + 384;
  int b = blockIdx.x;
  int g = threadIdx.x;
  float w[96];
  {
    const float4* wlo = (const float4*)(Whh + (size_t)g*128);
    #pragma unroll
    for(int i=0;i<24;i++){ float4 q=wlo[i]; w[4*i]=q.x; w[4*i+1]=q.y; w[4*i+2]=q.z; w[4*i+3]=q.w; }
    const float4* whi = (const float4*)(Whh + (size_t)g*128 + 96);
    #pragma unroll
    for(int i=0;i<8;i++) ((float4*)whh_s)[i*384 + g] = whi[i];
  }
  float bias = bhh[g];
  if(g<128) hs[g] = 0.0f;
  __syncthreads();

  float giv = g_gi[(size_t)b*GG + g];
  for(int s=0;s<SS;s++){
    float gi_next = 0.0f;
    if(s+1<SS) gi_next = g_gi[((size_t)(s+1)*BB + b)*GG + g];
    gis[g] = giv;
    float a0=0,a1=0,a2=0,a3=0;
    #pragma unroll
    for(int i=0;i<24;i++){
      float4 hv = ((float4*)hs)[i];
      a0 += w[4*i]*hv.x;   a1 += w[4*i+1]*hv.y;
      a2 += w[4*i+2]*hv.z; a3 += w[4*i+3]*hv.w;
    }
    #pragma unroll
    for(int i=0;i<8;i++){
      float4 wv = ((float4*)whh_s)[i*384 + g];
      float4 hv = ((float4*)hs)[24 + i];
      a0 += wv.x*hv.x; a1 += wv.y*hv.y; a2 += wv.z*hv.z; a3 += wv.w*hv.w;
    }
    ghs[g] = (a0+a1)+(a2+a3) + bias;
    __syncthreads();
    if(g<128){
      float rr = sig_acc(gis[g]       + ghs[g]);
      float zz = sig_acc(gis[128+g]   + ghs[128+g]);
      float nn = tanhf (gis[256+g] + rr*ghs[256+g]);
      float hn = (1.0f-zz)*nn + zz*hs[g];
      g_eoT[((size_t)b*SS + s)*HH + g] = hn;
      hs[g] = hn;
    }
    __syncthreads();
    giv = gi_next;
  }
  if(g<128) g_h[b*HH + g] = hs[g];
}

// ---------------- enc_proj ----------------
__global__ void __launch_bounds__(256,2) k_encproj(const float* __restrict__ attnW,
                                                   const float* __restrict__ attnb){
  int t = threadIdx.x;
  int j = t & 127, half = t >> 7;
  float w[64];
  const float4* wp = (const float4*)(attnW + (size_t)j*256 + 128 + half*64);
  #pragma unroll
  for(int i=0;i<16;i++){ float4 q=wp[i]; w[4*i]=q.x; w[4*i+1]=q.y; w[4*i+2]=q.z; w[4*i+3]=q.w; }
  float bias = attnb[j];
  __shared__ float xs[2][128];
  __shared__ float part[2][128];
  const int ROWS = (SS*BB)/512;
  size_t base = (size_t)blockIdx.x * ROWS;
  if(t<128) xs[0][t] = g_eoT[base*HH + t];
  __syncthreads();
  for(int r=0;r<ROWS;r++){
    int cur=r&1, nxt=cur^1;
    if(r+1<ROWS && t<128) xs[nxt][t] = g_eoT[(base+r+1)*HH + t];
    float a0=0,a1=0,a2=0,a3=0;
    const float* xp = &xs[cur][half*64];
    #pragma unroll
    for(int k=0;k<64;k+=4){
      a0+=w[k]*xp[k]; a1+=w[k+1]*xp[k+1]; a2+=w[k+2]*xp[k+2]; a3+=w[k+3]*xp[k+3];
    }
    part[half][j] = (a0+a1)+(a2+a3);
    __syncthreads();
    if(!half) g_epBS[(base+r)*HH + j] = part[0][j] + part[1][j] + bias;
    __syncthreads();
  }
}

// ---------------- convert enc_out to fp16 [b][s][h] ----------------
__global__ void k_eo16(){
  size_t i4 = (size_t)blockIdx.x*256 + threadIdx.x;
  float4 v = ((const float4*)g_eoT)[i4];
  uint2 o;
  o.x = pack_h2(__float2half_rn(v.x), __float2half_rn(v.y));
  o.y = pack_h2(__float2half_rn(v.z), __float2half_rn(v.w));
  ((uint2*)g_eo16)[i4] = o;
}

// ---------------- per-b transpose enc_proj -> fp16 [b][h][s] ----------------
__global__ void k_trP2(){
  __shared__ float tile[32][33];
  int b = blockIdx.z;
  int s0 = blockIdx.x*32, h0 = blockIdx.y*32;
  int tx = threadIdx.x, ty = threadIdx.y;
  #pragma unroll
  for(int i=0;i<32;i+=8)
    tile[ty+i][tx] = g_epBS[((size_t)b*SS + s0+ty+i)*HH + h0+tx];
  __syncthreads();
  #pragma unroll
  for(int i=0;i<32;i+=8)
    g_epT[((size_t)b*HH + h0+ty+i)*SS + s0+tx] = __float2half_rn(tile[tx][ty+i]);
}

// ---------------- attention (fp16 streams) ----------------
struct SAtt {
  float hs[128], hp[128], part[128], vsd[128];
  float ws[1024];
  float red[40];
  float4 cbuf[8][32];
};

__device__ void att_work(SAtt* S, int b, const float* __restrict__ attnW,
                         const float* __restrict__ attnv){
  int tid = threadIdx.x, lane = tid&31, warp = tid>>5;
  if(tid<128){ S->hs[tid] = g_h[b*HH + tid]; S->vsd[tid] = attnv[tid]; }
  __syncthreads();
  // hp = h @ attn_W[:, :128].T
  {
    int j = tid & 127, half = tid >> 7;
    const float4* wr = (const float4*)(attnW + (size_t)j*256 + half*64);
    const float* hb = &S->hs[half*64];
    float a = 0.0f;
    #pragma unroll
    for(int i=0;i<16;i++){
      float4 q = wr[i];
      a += q.x*hb[4*i] + q.y*hb[4*i+1] + q.z*hb[4*i+2] + q.w*hb[4*i+3];
    }
    if(half) S->part[j] = a;
    __syncthreads();
    if(!half) S->hp[j] = a + S->part[j];
    __syncthreads();
  }
  // scores: fp16 half2 loads
  {
    const __half2* base = (const __half2*)(g_epT + (size_t)b*HH*SS);
    float a0=0,a1=0,a2=0,a3=0;
    #pragma unroll 4
    for(int h=0;h<128;h++){
      float hpv = S->hp[h], vv = S->vsd[h];
      const __half2* p = base + h*(SS/2) + tid;
      __half2 q0 = p[0];
      __half2 q1 = p[256];
      float e0 = __low2float(q0), e1 = __high2float(q0);
      float e2 = __low2float(q1), e3 = __high2float(q1);
      a0 += tanh_fast(e0+hpv)*vv;
      a1 += tanh_fast(e1+hpv)*vv;
      a2 += tanh_fast(e2+hpv)*vv;
      a3 += tanh_fast(e3+hpv)*vv;
    }
    S->ws[2*tid]=a0; S->ws[2*tid+1]=a1;
    S->ws[512+2*tid]=a2; S->ws[512+2*tid+1]=a3;
  }
  __syncthreads();
  // softmax
  {
    float4 sc = ((float4*)S->ws)[tid];
    float m = fmaxf(fmaxf(sc.x,sc.y), fmaxf(sc.z,sc.w));
    #pragma unroll
    for(int o=16;o;o>>=1) m = fmaxf(m, __shfl_xor_sync(0xffffffffu,m,o));
    if(lane==0) S->red[warp] = m;
    __syncthreads();
    if(tid==0){ float mm=S->red[0]; for(int i=1;i<8;i++) mm=fmaxf(mm,S->red[i]); S->red[8]=mm; }
    __syncthreads();
    float M = S->red[8];
    float4 e;
    e.x=expf(sc.x-M); e.y=expf(sc.y-M); e.z=expf(sc.z-M); e.w=expf(sc.w-M);
    ((float4*)S->ws)[tid] = e;
    float ssum = (e.x+e.y)+(e.z+e.w);
    #pragma unroll
    for(int o=16;o;o>>=1) ssum += __shfl_xor_sync(0xffffffffu, ssum, o);
    if(lane==0) S->red[16+warp] = ssum;
    __syncthreads();
    if(tid==0){ float s2=0; for(int i=0;i<8;i++) s2+=S->red[16+i]; S->red[24]=s2; }
    __syncthreads();
  }
  float inv = 1.0f / S->red[24];
  // context: fp16 eo reads
  {
    int hq = tid&31, sg = tid>>5;
    const uint2* base = (const uint2*)(g_eo16 + (size_t)b*SS*HH);
    float4 acc = make_float4(0,0,0,0);
    #pragma unroll 4
    for(int i=0;i<128;i++){
      int s = sg + (i<<3);
      float wg = S->ws[s];
      uint2 raw = base[s*32 + hq];
      __half2 ab = *(__half2*)&raw.x;
      __half2 cd = *(__half2*)&raw.y;
      acc.x += wg*__low2float(ab); acc.y += wg*__high2float(ab);
      acc.z += wg*__low2float(cd); acc.w += wg*__high2float(cd);
    }
    S->cbuf[sg][hq] = acc;
    __syncthreads();
    if(tid<32){
      float4 tot = S->cbuf[0][tid];
      #pragma unroll
      for(int g2=1;g2<8;g2++){
        float4 c = S->cbuf[g2][tid];
        tot.x+=c.x; tot.y+=c.y; tot.z+=c.z; tot.w+=c.w;
      }
      tot.x*=inv; tot.y*=inv; tot.z*=inv; tot.w*=inv;
      int h0 = tid*4;
      S->part[h0]=tot.x; S->part[h0+1]=tot.y; S->part[h0+2]=tot.z; S->part[h0+3]=tot.w;
      g_ctx[b*HH+h0]=tot.x; g_ctx[b*HH+h0+1]=tot.y;
      g_ctx[b*HH+h0+2]=tot.z; g_ctx[b*HH+h0+3]=tot.w;
    }
  }
  __syncthreads();
  // gh = Whh.h ; gic = Wih[:,64:].ctx (no biases)
  if(tid < 192){
    float g0=0,g1=0,c0=0,c1=0;
    #pragma unroll 4
    for(int k=0;k<128;k++){
      float2 wh2 = g_whT2[k*192 + tid];
      float2 wi2 = g_wiT2[(64+k)*192 + tid];
      float hv = S->hs[k], cv = S->part[k];
      g0 += wh2.x*hv; g1 += wh2.y*hv;
      c0 += wi2.x*cv; c1 += wi2.y*cv;
    }
    g_gh[b*GG+2*tid]=g0;  g_gh[b*GG+2*tid+1]=g1;
    g_gic[b*GG+2*tid]=c0; g_gic[b*GG+2*tid+1]=c1;
  }
}

// ---------------- setup attention (step 0) ----------------
__global__ void __launch_bounds__(256,1) k_att0(const float* __restrict__ attnW,
                                                const float* __restrict__ attnv){
  __shared__ SAtt satt;
  att_work(&satt, blockIdx.x, attnW, attnv);
}

// ---------------- decoder GRU (serial-path kernel) ----------------
__global__ void __launch_bounds__(256,4) k_gru(const int* __restrict__ seq,
      const float* __restrict__ emb, const float* __restrict__ dbih,
      const float* __restrict__ dbhh, int t){
  __shared__ float embs[64], gi[384], gh[384], hold[128], hnew[128], ctxs[128];
  __shared__ float sv[8]; __shared__ int si8[8]; __shared__ int stok;
  int b = blockIdx.x, tid = threadIdx.x;
  int lane = tid&31, warp = tid>>5;
  if(t == 0){
    if(tid==0) stok = seq[b];
  } else {
    float v=-3.4e38f; int ix=0x7fffffff;
    for(int idx=tid; idx<NTILES; idx+=256){
      float pv = g_pval[(size_t)b*2048+idx]; int pi = g_pidx[(size_t)b*2048+idx];
      if(pv>v || (pv==v && pi<ix)){ v=pv; ix=pi; }
    }
    #pragma unroll
    for(int o=16;o;o>>=1){
      float ov=__shfl_xor_sync(0xffffffffu,v,o); int oi=__shfl_xor_sync(0xffffffffu,ix,o);
      if(ov>v || (ov==v && oi<ix)){ v=ov; ix=oi; }
    }
    if(lane==0){ sv[warp]=v; si8[warp]=ix; }
    __syncthreads();
    if(tid==0){
      float bv=sv[0]; int bx=si8[0];
      for(int i=1;i<8;i++) if(sv[i]>bv || (sv[i]==bv && si8[i]<bx)){ bv=sv[i]; bx=si8[i]; }
      stok = bx;
    }
  }
  __syncthreads();
  if(tid < 64) embs[tid] = emb[(size_t)stok*EE + tid];
  if(tid < 128){ hold[tid] = g_h[b*HH + tid]; ctxs[tid] = g_ctx[b*HH + tid]; }
  __syncthreads();
  if(tid < 192){
    float a0 = dbih[2*tid]   + g_gic[b*GG+2*tid];
    float a1 = dbih[2*tid+1] + g_gic[b*GG+2*tid+1];
    #pragma unroll 8
    for(int k=0;k<64;k++){
      float2 w = g_wiT2[k*192 + tid];
      float x = embs[k];
      a0 += w.x*x; a1 += w.y*x;
    }
    gi[2*tid]=a0; gi[2*tid+1]=a1;
    gh[2*tid]   = dbhh[2*tid]   + g_gh[b*GG+2*tid];
    gh[2*tid+1] = dbhh[2*tid+1] + g_gh[b*GG+2*tid+1];
  }
  __syncthreads();
  if(tid < 128){
    float rr = sig_acc(gi[tid]     + gh[tid]);
    float zz = sig_acc(gi[128+tid] + gh[128+tid]);
    float nn = tanhf (gi[256+tid] + rr*gh[256+tid]);
    float hv = (1.0f-zz)*nn + zz*hold[tid];
    g_h[b*HH + tid] = hv;
    hnew[tid] = hv;
  }
  __syncthreads();
  if(tid < 128){
    float f0, f1;
    if(tid < 64){ f0 = hnew[2*tid]; f1 = hnew[2*tid+1]; }
    else        { f0 = ctxs[2*tid-128]; f1 = ctxs[2*tid-127]; }
    uint32_t h,m;
    split2h(make_float2(f0,f1), h, m);
    g_xh[b*128+tid]=h; g_xm[b*128+tid]=m;
  }
}

// ---------------- fused: attention(t+1) || logits(t) tile pool (NT2=16) ----------------
#define BSTR 528u
#define SPL (16u*BSTR)          // 8448
#define BUFB (2u*SPL)           // 16896
#define LOG_DYN (2*BUFB)        // 33792
__global__ void __launch_bounds__(256,3) k_fused(const float* __restrict__ attnW,
      const float* __restrict__ attnv, const float* __restrict__ outb,
      float* __restrict__ out, int t, int do_att, int slot){
  extern __shared__ char dyn[];
  __shared__ SAtt satt;
  __shared__ int s_tile;
  int cta = blockIdx.x, tid = threadIdx.x;
  int lane = tid&31, warp = tid>>5;
  uint32_t sb = s2u(dyn);

  // ---- prefetch first (static) weight tile ----
  int cur = cta;                           // tile id < GRID < NTILES
  {
    const char* sH = (const char*)g_Wh + (size_t)cur*NT2*512;
    const char* sM = (const char*)g_Wm + (size_t)cur*NT2*512;
    #pragma unroll
    for(int j=0;j<2;j++){
      int idx = tid + j*256;               // 0..511
      uint32_t off = (uint32_t)(idx>>5)*BSTR + (uint32_t)(idx&31)*16u;
      cpasync16(sb + off,       sH + (size_t)idx*16);
      cpasync16(sb + SPL + off, sM + (size_t)idx*16);
    }
    asm volatile("cp.async.commit_group;" ::: "memory");
  }

  // ---- attention for next step (CTAs 0..127) ----
  if(do_att && cta < 128) att_work(&satt, cta, attnW, attnv);

  // ---- logits tile pool ----
  int r = lane>>2, tig = lane&3;
  int b0 = warp*16 + r, b1 = b0 + 8;
  uint32_t lrow = (uint32_t)(lane&7) + (uint32_t)((lane>>4)<<3);
  uint32_t lkadd = (uint32_t)(((lane>>3)&1)<<4);
  float* outRow = out + (size_t)t*BB*VV;
  const float INVS = 1.0f/2048.0f;
  int* tctr = &g_tctr[slot];

  int bufi = 0;
  while(cur < NTILES){
    __syncthreads();
    if(tid==0) s_tile = atomicAdd(tctr, 1);
    __syncthreads();
    int nxt = s_tile;
    uint32_t curb = sb + (bufi ? BUFB : 0u);
    uint32_t nxtb = sb + (bufi ? 0u : BUFB);
    if(nxt < NTILES){
      const char* sH = (const char*)g_Wh + (size_t)nxt*NT2*512;
      const char* sM = (const char*)g_Wm + (size_t)nxt*NT2*512;
      #pragma unroll
      for(int j=0;j<2;j++){
        int idx = tid + j*256;             // 0..511
        uint32_t off = (uint32_t)(idx>>5)*BSTR + (uint32_t)(idx&31)*16u;
        cpasync16(nxtb + off,       sH + (size_t)idx*16);
        cpasync16(nxtb + SPL + off, sM + (size_t)idx*16);
      }
    }
    asm volatile("cp.async.commit_group;" ::: "memory");
    asm volatile("cp.async.wait_group 1;" ::: "memory");
    __syncthreads();

    int v0 = cur*NT2;
    float c1[2][4], c2[2][4];
    #pragma unroll
    for(int i=0;i<2;i++){
      c1[i][0]=0.f;c1[i][1]=0.f;c1[i][2]=0.f;c1[i][3]=0.f;
      c2[i][0]=0.f;c2[i][1]=0.f;c2[i][2]=0.f;c2[i][3]=0.f;
    }
    #pragma unroll
    for(int kc=0;kc<2;kc++){
      int base0 = b0*128 + kc*64 + tig;
      int base1 = b1*128 + kc*64 + tig;
      #pragma unroll
      for(int ks=0;ks<8;ks++){
        int i0 = base0 + ks*8, i1 = base1 + ks*8;
        uint32_t ah[4], am[4];
        ah[0]=g_xh[i0]; ah[1]=g_xh[i1]; ah[2]=g_xh[i0+4]; ah[3]=g_xh[i1+4];
        am[0]=g_xm[i0]; am[1]=g_xm[i1]; am[2]=g_xm[i0+4]; am[3]=g_xm[i1+4];
        uint32_t kb = (uint32_t)(kc*128 + ks*16)*2u;
        uint32_t rowoff = lrow*BSTR + kb + lkadd;
        uint32_t h0a,h1a,h0b,h1b, m0a,m1a,m0b,m1b;
        LDSM4(h0a,h1a,h0b,h1b, curb + rowoff);
        LDSM4(m0a,m1a,m0b,m1b, curb + SPL + rowoff);
        MMA(c1[0], ah, h0a,h1a);
        MMA(c2[0], ah, m0a,m1a);
        MMA(c2[0], am, h0a,h1a);
        MMA(c1[1], ah, h0b,h1b);
        MMA(c2[1], ah, m0b,m1b);
        MMA(c2[1], am, h0b,h1b);
      }
    }
    // epilogue
    float bv0=-3.4e38f, bv1=-3.4e38f; int bi0=0x7fffffff, bi1=0x7fffffff;
    #pragma unroll
    for(int ns=0;ns<2;ns++){
      int n = ns*8 + tig*2;
      float2 bb = *(const float2*)(outb + v0 + n);
      float f0 = c1[ns][0] + c2[ns][0]*INVS + bb.x;
      float f1 = c1[ns][1] + c2[ns][1]*INVS + bb.y;
      float f2 = c1[ns][2] + c2[ns][2]*INVS + bb.x;
      float f3 = c1[ns][3] + c2[ns][3]*INVS + bb.y;
      if(f0>bv0){bv0=f0;bi0=v0+n;}
      if(f1>bv0){bv0=f1;bi0=v0+n+1;}
      if(f2>bv1){bv1=f2;bi1=v0+n;}
      if(f3>bv1){bv1=f3;bi1=v0+n+1;}
      *(float2*)(outRow + (size_t)b0*VV + v0 + n) = make_float2(f0,f1);
      *(float2*)(outRow + (size_t)b1*VV + v0 + n) = make_float2(f2,f3);
    }
    #pragma unroll
    for(int o=1;o<4;o<<=1){
      float ov0=__shfl_xor_sync(0xffffffffu,bv0,o); int oi0=__shfl_xor_sync(0xffffffffu,bi0,o);
      float ov1=__shfl_xor_sync(0xffffffffu,bv1,o); int oi1=__shfl_xor_sync(0xffffffffu,bi1,o);
      if(ov0>bv0||(ov0==bv0&&oi0<bi0)){bv0=ov0;bi0=oi0;}
      if(ov1>bv1||(ov1==bv1&&oi1<bi1)){bv1=ov1;bi1=oi1;}
    }
    if(tig==0){
      g_pval[(size_t)b0*2048 + cur]=bv0; g_pidx[(size_t)b0*2048 + cur]=bi0;
      g_pval[(size_t)b1*2048 + cur]=bv1; g_pidx[(size_t)b1*2048 + cur]=bi1;
    }
    cur = nxt;
    bufi ^= 1;
  }
}

// ---------------- launch ----------------
extern "C" void kernel_launch(void* const* d_in, const int* in_sizes, int n_in,
                              void* d_out, int out_size) {
  const int*   seq     = (const int*)  d_in[0];
  const float* emb     = (const float*)d_in[2];
  const float* encWih  = (const float*)d_in[3];
  const float* encWhh  = (const float*)d_in[4];
  const float* encbih  = (const float*)d_in[5];
  const float* encbhh  = (const float*)d_in[6];
  const float* attnW   = (const float*)d_in[7];
  const float* attnb   = (const float*)d_in[8];
  const float* attnv   = (const float*)d_in[9];
  const float* dWih    = (const float*)d_in[10];
  const float* dWhh    = (const float*)d_in[11];
  const float* dbih    = (const float*)d_in[12];
  const float* dbhh    = (const float*)d_in[13];
  const float* outW    = (const float*)d_in[14];
  const float* outb    = (const float*)d_in[15];
  float* out = (float*)d_out;

  const int ENC_SMEM = (12288 + 128 + 384 + 384) * 4;
  cudaFuncSetAttribute(k_encrec, cudaFuncAttributeMaxDynamicSharedMemorySize, ENC_SMEM);
  cudaFuncSetAttribute(k_fused,  cudaFuncAttributeMaxDynamicSharedMemorySize, LOG_DYN);

  // setup (probe stays at kernel launch #4 for ncu visibility)
  k_wsplit<<<8000, 256>>>(outW);
  k_wtrans<<<240, 256>>>(dWih, dWhh);
  k_giall<<<512, 384>>>(seq, emb, encWih, encbih);   // resets g_tctr
  // PROFILING PROBE: dummy decode kernel (att on, counter slot TT). All outputs
  // overwritten by later launches every call -> deterministic final state.
  k_fused<<<GRID, 256, LOG_DYN>>>(attnW, attnv, outb, out, 0, 1, TT);
  k_encrec<<<128, 384, ENC_SMEM>>>(encWhh, encbhh);
  k_encproj<<<512, 256>>>(attnW, attnb);
  k_eo16<<<16384, 256>>>();
  k_trP2<<<dim3(32,4,128), dim3(32,8)>>>();
  k_att0<<<128, 256>>>(attnW, attnv);   // attention state for step 0

  // decode: 2 kernels per step; attention(t+1) overlaps logits(t)
  for(int t=0; t<TT; t++){
    k_gru<<<128, 256>>>(seq, emb, dbih, dbhh, t);
    k_fused<<<GRID, 256, LOG_DYN>>>(attnW, attnv, outb, out, t, (t < TT-1) ? 1 : 0, t);
  }
}

// round 16
// speedup vs baseline: 1.1898x; 1.1898x over previous
#include <cuda_runtime.h>
#include <cuda_bf16.h>
#include <cuda_fp16.h>
#include <math.h>
#include <stdint.h>

#define VV 32000
#define EE 64
#define HH 128
#define SS 1024
#define BB 128
#define TT 64
#define GG 384
#define NT2 32
#define NTILES 1000        // VV / NT2
#define GRID 256

// ---------------- device scratch ----------------
__device__ float g_gi[(size_t)SS*BB*GG];
__device__ float g_eoT[(size_t)BB*SS*HH];     // enc_out [b][s][h] fp32
__device__ __half g_eo16[(size_t)BB*SS*HH];   // enc_out [b][s][h] fp16 (context reads)
__device__ float g_epBS[(size_t)BB*SS*HH];    // enc_proj [b][s][h] fp32
__device__ __half g_epT[(size_t)BB*HH*SS];    // enc_proj [b][h][s] fp16 (score reads)
__device__ __half g_Wh[(size_t)VV*256];       // fp16 high split [v][k]
__device__ __half g_Wm[(size_t)VV*256];       // fp16 residual * 2048
__device__ float2 g_wiT2[192*192];            // [k][jpair] of dec_Wih
__device__ float2 g_whT2[128*192];            // [k][jpair] of dec_Whh
__device__ float g_h[BB*HH];
__device__ float g_ctx[BB*HH];                // ctx for current step
__device__ float g_gh[BB*GG];                 // Whh . h (no bias)
__device__ float g_gic[BB*GG];                // Wih[:,64:] . ctx (no bias)
__device__ uint32_t g_xh[BB*128];             // x fp16x2 high split [b][pair]
__device__ uint32_t g_xm[BB*128];             // x fp16x2 residual*2048
__device__ float g_pval[(size_t)BB*1024];
__device__ int   g_pidx[(size_t)BB*1024];
__device__ int   g_tctr[TT+1];                // per-step tile counters

__device__ __forceinline__ float sig_acc(float x){ return 1.0f/(1.0f + expf(-x)); }
// 1-MUFU tanh: exp via MUFU, reciprocal via bit-trick + 3 Newton iters (~1e-8 rel err)
__device__ __forceinline__ float tanh_fast(float x){
  x = fminf(fmaxf(x, -10.0f), 10.0f);
  float e = __expf(2.0f*x);
  float y = 1.0f + e;
  float u = __uint_as_float(0x7EF311C3u - __float_as_uint(y));
  u = u*(2.0f - y*u);
  u = u*(2.0f - y*u);
  u = u*(2.0f - y*u);
  return 1.0f - 2.0f*u;
}

// ---------------- helpers ----------------
__device__ __forceinline__ uint32_t s2u(const void* p){
  uint32_t a;
  asm("{ .reg .u64 t; cvta.to.shared.u64 t, %1; cvt.u32.u64 %0, t; }" : "=r"(a) : "l"(p));
  return a;
}
__device__ __forceinline__ uint32_t pack_h2(__half lo, __half hi){
  __half2 t = __halves2half2(lo, hi);
  return *(uint32_t*)&t;
}
__device__ __forceinline__ void split2h(float2 f, uint32_t& h, uint32_t& m){
  __half h0=__float2half_rn(f.x), h1=__float2half_rn(f.y);
  float r0=(f.x-__half2float(h0))*2048.0f, r1=(f.y-__half2float(h1))*2048.0f;
  h = pack_h2(h0,h1);
  m = pack_h2(__float2half_rn(r0), __float2half_rn(r1));
}
__device__ __forceinline__ void cpasync16(uint32_t saddr, const void* gaddr){
  asm volatile("cp.async.cg.shared.global [%0], [%1], 16;" :: "r"(saddr), "l"(gaddr) : "memory");
}

#define MMA(cc, aa, bb0, bb1) \
  asm volatile("mma.sync.aligned.m16n8k16.row.col.f32.f16.f16.f32 " \
    "{%0,%1,%2,%3}, {%4,%5,%6,%7}, {%8,%9}, {%0,%1,%2,%3};" \
    : "+f"(cc[0]),"+f"(cc[1]),"+f"(cc[2]),"+f"(cc[3]) \
    : "r"(aa[0]),"r"(aa[1]),"r"(aa[2]),"r"(aa[3]), "r"(bb0),"r"(bb1))

#define LDSM4(r0,r1,r2,r3,addr) \
  asm volatile("ldmatrix.sync.aligned.m8n8.x4.shared.b16 {%0,%1,%2,%3}, [%4];" \
    : "=r"(r0),"=r"(r1),"=r"(r2),"=r"(r3) : "r"(addr))

// ---------------- setup: split out_W into 2 fp16 levels ----------------
__global__ void k_wsplit(const float* __restrict__ outW){
  size_t i4 = (size_t)blockIdx.x*256 + threadIdx.x;
  float4 w = ((const float4*)outW)[i4];
  uint2 uh, um;
  split2h(make_float2(w.x,w.y), uh.x, um.x);
  split2h(make_float2(w.z,w.w), uh.y, um.y);
  ((uint2*)g_Wh)[i4] = uh;
  ((uint2*)g_Wm)[i4] = um;
}

// ---------------- setup: transpose decoder GRU weights ----------------
__global__ void k_wtrans(const float* __restrict__ dWih, const float* __restrict__ dWhh){
  int idx = blockIdx.x*256 + threadIdx.x;
  if(idx < 192*192){
    int k = idx/192, j = idx%192;
    g_wiT2[idx] = make_float2(dWih[(size_t)(2*j)*192+k], dWih[(size_t)(2*j+1)*192+k]);
  } else {
    int i2 = idx - 192*192;
    if(i2 < 128*192){
      int k = i2/192, j = i2%192;
      g_whT2[i2] = make_float2(dWhh[(size_t)(2*j)*128+k], dWhh[(size_t)(2*j+1)*128+k]);
    }
  }
}

// ---------------- encoder input projection (also resets tile counters) ----------------
__global__ void __launch_bounds__(384,2) k_giall(const int* __restrict__ seq,
      const float* __restrict__ emb, const float* __restrict__ Wih,
      const float* __restrict__ bih){
  if(blockIdx.x==0 && threadIdx.x < TT+1) g_tctr[threadIdx.x] = GRID;
  int g = threadIdx.x;
  float w[64];
  const float4* wp = (const float4*)(Wih + (size_t)g*64);
  #pragma unroll
  for(int i=0;i<16;i++){ float4 q=wp[i]; w[4*i]=q.x; w[4*i+1]=q.y; w[4*i+2]=q.z; w[4*i+3]=q.w; }
  float bias = bih[g];
  __shared__ float xs[2][64];
  const int ROWS = (SS*BB)/512;
  size_t base = (size_t)blockIdx.x * ROWS;
  if(g<64){ int tok0 = seq[base]; xs[0][g] = emb[(size_t)tok0*EE + g]; }
  __syncthreads();
  for(int r=0;r<ROWS;r++){
    int cur=r&1, nxt=cur^1;
    if(r+1<ROWS && g<64){
      int tok2 = seq[base+r+1];
      xs[nxt][g] = emb[(size_t)tok2*EE + g];
    }
    float a0=0,a1=0,a2=0,a3=0;
    #pragma unroll
    for(int k=0;k<64;k+=4){
      a0 += w[k]*xs[cur][k];     a1 += w[k+1]*xs[cur][k+1];
      a2 += w[k+2]*xs[cur][k+2]; a3 += w[k+3]*xs[cur][k+3];
    }
    g_gi[(base+r)*GG + g] = (a0+a1)+(a2+a3) + bias;
    __syncthreads();
  }
}

// ---------------- encoder recurrence ----------------
__global__ void __launch_bounds__(384,1) k_encrec(const float* __restrict__ Whh,
      const float* __restrict__ bhh){
  extern __shared__ float sm[];
  float* whh_s = sm;
  float* hs    = sm + 12288;
  float* ghs   = hs + 128;
  float* gis   = ghs + 384;
  int b = blockIdx.x;
  int g = threadIdx.x;
  float w[96];
  {
    const float4* wlo = (const float4*)(Whh + (size_t)g*128);
    #pragma unroll
    for(int i=0;i<24;i++){ float4 q=wlo[i]; w[4*i]=q.x; w[4*i+1]=q.y; w[4*i+2]=q.z; w[4*i+3]=q.w; }
    const float4* whi = (const float4*)(Whh + (size_t)g*128 + 96);
    #pragma unroll
    for(int i=0;i<8;i++) ((float4*)whh_s)[i*384 + g] = whi[i];
  }
  float bias = bhh[g];
  if(g<128) hs[g] = 0.0f;
  __syncthreads();

  float giv = g_gi[(size_t)b*GG + g];
  for(int s=0;s<SS;s++){
    float gi_next = 0.0f;
    if(s+1<SS) gi_next = g_gi[((size_t)(s+1)*BB + b)*GG + g];
    gis[g] = giv;
    float a0=0,a1=0,a2=0,a3=0;
    #pragma unroll
    for(int i=0;i<24;i++){
      float4 hv = ((float4*)hs)[i];
      a0 += w[4*i]*hv.x;   a1 += w[4*i+1]*hv.y;
      a2 += w[4*i+2]*hv.z; a3 += w[4*i+3]*hv.w;
    }
    #pragma unroll
    for(int i=0;i<8;i++){
      float4 wv = ((float4*)whh_s)[i*384 + g];
      float4 hv = ((float4*)hs)[24 + i];
      a0 += wv.x*hv.x; a1 += wv.y*hv.y; a2 += wv.z*hv.z; a3 += wv.w*hv.w;
    }
    ghs[g] = (a0+a1)+(a2+a3) + bias;
    __syncthreads();
    if(g<128){
      float rr = sig_acc(gis[g]       + ghs[g]);
      float zz = sig_acc(gis[128+g]   + ghs[128+g]);
      float nn = tanhf (gis[256+g] + rr*ghs[256+g]);
      float hn = (1.0f-zz)*nn + zz*hs[g];
      g_eoT[((size_t)b*SS + s)*HH + g] = hn;
      hs[g] = hn;
    }
    __syncthreads();
    giv = gi_next;
  }
  if(g<128) g_h[b*HH + g] = hs[g];
}

// ---------------- enc_proj ----------------
__global__ void __launch_bounds__(256,2) k_encproj(const float* __restrict__ attnW,
                                                   const float* __restrict__ attnb){
  int t = threadIdx.x;
  int j = t & 127, half = t >> 7;
  float w[64];
  const float4* wp = (const float4*)(attnW + (size_t)j*256 + 128 + half*64);
  #pragma unroll
  for(int i=0;i<16;i++){ float4 q=wp[i]; w[4*i]=q.x; w[4*i+1]=q.y; w[4*i+2]=q.z; w[4*i+3]=q.w; }
  float bias = attnb[j];
  __shared__ float xs[2][128];
  __shared__ float part[2][128];
  const int ROWS = (SS*BB)/512;
  size_t base = (size_t)blockIdx.x * ROWS;
  if(t<128) xs[0][t] = g_eoT[base*HH + t];
  __syncthreads();
  for(int r=0;r<ROWS;r++){
    int cur=r&1, nxt=cur^1;
    if(r+1<ROWS && t<128) xs[nxt][t] = g_eoT[(base+r+1)*HH + t];
    float a0=0,a1=0,a2=0,a3=0;
    const float* xp = &xs[cur][half*64];
    #pragma unroll
    for(int k=0;k<64;k+=4){
      a0+=w[k]*xp[k]; a1+=w[k+1]*xp[k+1]; a2+=w[k+2]*xp[k+2]; a3+=w[k+3]*xp[k+3];
    }
    part[half][j] = (a0+a1)+(a2+a3);
    __syncthreads();
    if(!half) g_epBS[(base+r)*HH + j] = part[0][j] + part[1][j] + bias;
    __syncthreads();
  }
}

// ---------------- convert enc_out to fp16 [b][s][h] ----------------
__global__ void k_eo16(){
  size_t i4 = (size_t)blockIdx.x*256 + threadIdx.x;
  float4 v = ((const float4*)g_eoT)[i4];
  uint2 o;
  o.x = pack_h2(__float2half_rn(v.x), __float2half_rn(v.y));
  o.y = pack_h2(__float2half_rn(v.z), __float2half_rn(v.w));
  ((uint2*)g_eo16)[i4] = o;
}

// ---------------- per-b transpose enc_proj -> fp16 [b][h][s] ----------------
__global__ void k_trP2(){
  __shared__ float tile[32][33];
  int b = blockIdx.z;
  int s0 = blockIdx.x*32, h0 = blockIdx.y*32;
  int tx = threadIdx.x, ty = threadIdx.y;
  #pragma unroll
  for(int i=0;i<32;i+=8)
    tile[ty+i][tx] = g_epBS[((size_t)b*SS + s0+ty+i)*HH + h0+tx];
  __syncthreads();
  #pragma unroll
  for(int i=0;i<32;i+=8)
    g_epT[((size_t)b*HH + h0+ty+i)*SS + s0+tx] = __float2half_rn(tile[tx][ty+i]);
}

// ---------------- attention (fp16 streams, 1-MUFU tanh) ----------------
struct SAtt {
  float hs[128], hp[128], part[128], vsd[128];
  float ws[1024];
  float red[40];
  float4 cbuf[8][32];
};

__device__ void att_work(SAtt* S, int b, const float* __restrict__ attnW,
                         const float* __restrict__ attnv){
  int tid = threadIdx.x, lane = tid&31, warp = tid>>5;
  if(tid<128){ S->hs[tid] = g_h[b*HH + tid]; S->vsd[tid] = attnv[tid]; }
  __syncthreads();
  // hp = h @ attn_W[:, :128].T
  {
    int j = tid & 127, half = tid >> 7;
    const float4* wr = (const float4*)(attnW + (size_t)j*256 + half*64);
    const float* hb = &S->hs[half*64];
    float a = 0.0f;
    #pragma unroll
    for(int i=0;i<16;i++){
      float4 q = wr[i];
      a += q.x*hb[4*i] + q.y*hb[4*i+1] + q.z*hb[4*i+2] + q.w*hb[4*i+3];
    }
    if(half) S->part[j] = a;
    __syncthreads();
    if(!half) S->hp[j] = a + S->part[j];
    __syncthreads();
  }
  // scores: fp16 half2 loads
  {
    const __half2* base = (const __half2*)(g_epT + (size_t)b*HH*SS);
    float a0=0,a1=0,a2=0,a3=0;
    #pragma unroll 4
    for(int h=0;h<128;h++){
      float hpv = S->hp[h], vv = S->vsd[h];
      const __half2* p = base + h*(SS/2) + tid;
      __half2 q0 = p[0];
      __half2 q1 = p[256];
      float e0 = __low2float(q0), e1 = __high2float(q0);
      float e2 = __low2float(q1), e3 = __high2float(q1);
      a0 += tanh_fast(e0+hpv)*vv;
      a1 += tanh_fast(e1+hpv)*vv;
      a2 += tanh_fast(e2+hpv)*vv;
      a3 += tanh_fast(e3+hpv)*vv;
    }
    S->ws[2*tid]=a0; S->ws[2*tid+1]=a1;
    S->ws[512+2*tid]=a2; S->ws[512+2*tid+1]=a3;
  }
  __syncthreads();
  // softmax
  {
    float4 sc = ((float4*)S->ws)[tid];
    float m = fmaxf(fmaxf(sc.x,sc.y), fmaxf(sc.z,sc.w));
    #pragma unroll
    for(int o=16;o;o>>=1) m = fmaxf(m, __shfl_xor_sync(0xffffffffu,m,o));
    if(lane==0) S->red[warp] = m;
    __syncthreads();
    if(tid==0){ float mm=S->red[0]; for(int i=1;i<8;i++) mm=fmaxf(mm,S->red[i]); S->red[8]=mm; }
    __syncthreads();
    float M = S->red[8];
    float4 e;
    e.x=expf(sc.x-M); e.y=expf(sc.y-M); e.z=expf(sc.z-M); e.w=expf(sc.w-M);
    ((float4*)S->ws)[tid] = e;
    float ssum = (e.x+e.y)+(e.z+e.w);
    #pragma unroll
    for(int o=16;o;o>>=1) ssum += __shfl_xor_sync(0xffffffffu, ssum, o);
    if(lane==0) S->red[16+warp] = ssum;
    __syncthreads();
    if(tid==0){ float s2=0; for(int i=0;i<8;i++) s2+=S->red[16+i]; S->red[24]=s2; }
    __syncthreads();
  }
  float inv = 1.0f / S->red[24];
  // context: fp16 eo reads
  {
    int hq = tid&31, sg = tid>>5;
    const uint2* base = (const uint2*)(g_eo16 + (size_t)b*SS*HH);
    float4 acc = make_float4(0,0,0,0);
    #pragma unroll 4
    for(int i=0;i<128;i++){
      int s = sg + (i<<3);
      float wg = S->ws[s];
      uint2 raw = base[s*32 + hq];
      __half2 ab = *(__half2*)&raw.x;
      __half2 cd = *(__half2*)&raw.y;
      acc.x += wg*__low2float(ab); acc.y += wg*__high2float(ab);
      acc.z += wg*__low2float(cd); acc.w += wg*__high2float(cd);
    }
    S->cbuf[sg][hq] = acc;
    __syncthreads();
    if(tid<32){
      float4 tot = S->cbuf[0][tid];
      #pragma unroll
      for(int g2=1;g2<8;g2++){
        float4 c = S->cbuf[g2][tid];
        tot.x+=c.x; tot.y+=c.y; tot.z+=c.z; tot.w+=c.w;
      }
      tot.x*=inv; tot.y*=inv; tot.z*=inv; tot.w*=inv;
      int h0 = tid*4;
      S->part[h0]=tot.x; S->part[h0+1]=tot.y; S->part[h0+2]=tot.z; S->part[h0+3]=tot.w;
      g_ctx[b*HH+h0]=tot.x; g_ctx[b*HH+h0+1]=tot.y;
      g_ctx[b*HH+h0+2]=tot.z; g_ctx[b*HH+h0+3]=tot.w;
    }
  }
  __syncthreads();
  // gh = Whh.h ; gic = Wih[:,64:].ctx (no biases)
  if(tid < 192){
    float g0=0,g1=0,c0=0,c1=0;
    #pragma unroll 4
    for(int k=0;k<128;k++){
      float2 wh2 = g_whT2[k*192 + tid];
      float2 wi2 = g_wiT2[(64+k)*192 + tid];
      float hv = S->hs[k], cv = S->part[k];
      g0 += wh2.x*hv; g1 += wh2.y*hv;
      c0 += wi2.x*cv; c1 += wi2.y*cv;
    }
    g_gh[b*GG+2*tid]=g0;  g_gh[b*GG+2*tid+1]=g1;
    g_gic[b*GG+2*tid]=c0; g_gic[b*GG+2*tid+1]=c1;
  }
}

// ---------------- setup attention (step 0) ----------------
__global__ void __launch_bounds__(256,1) k_att0(const float* __restrict__ attnW,
                                                const float* __restrict__ attnv){
  __shared__ SAtt satt;
  att_work(&satt, blockIdx.x, attnW, attnv);
}

// ---------------- decoder GRU (serial-path kernel) ----------------
__global__ void __launch_bounds__(256,4) k_gru(const int* __restrict__ seq,
      const float* __restrict__ emb, const float* __restrict__ dbih,
      const float* __restrict__ dbhh, int t){
  __shared__ float embs[64], gi[384], gh[384], hold[128], hnew[128], ctxs[128];
  __shared__ float sv[8]; __shared__ int si8[8]; __shared__ int stok;
  int b = blockIdx.x, tid = threadIdx.x;
  int lane = tid&31, warp = tid>>5;
  if(t == 0){
    if(tid==0) stok = seq[b];
  } else {
    float v=-3.4e38f; int ix=0x7fffffff;
    for(int idx=tid; idx<NTILES; idx+=256){
      float pv = g_pval[(size_t)b*1024+idx]; int pi = g_pidx[(size_t)b*1024+idx];
      if(pv>v || (pv==v && pi<ix)){ v=pv; ix=pi; }
    }
    #pragma unroll
    for(int o=16;o;o>>=1){
      float ov=__shfl_xor_sync(0xffffffffu,v,o); int oi=__shfl_xor_sync(0xffffffffu,ix,o);
      if(ov>v || (ov==v && oi<ix)){ v=ov; ix=oi; }
    }
    if(lane==0){ sv[warp]=v; si8[warp]=ix; }
    __syncthreads();
    if(tid==0){
      float bv=sv[0]; int bx=si8[0];
      for(int i=1;i<8;i++) if(sv[i]>bv || (sv[i]==bv && si8[i]<bx)){ bv=sv[i]; bx=si8[i]; }
      stok = bx;
    }
  }
  __syncthreads();
  if(tid < 64) embs[tid] = emb[(size_t)stok*EE + tid];
  if(tid < 128){ hold[tid] = g_h[b*HH + tid]; ctxs[tid] = g_ctx[b*HH + tid]; }
  __syncthreads();
  if(tid < 192){
    float a0 = dbih[2*tid]   + g_gic[b*GG+2*tid];
    float a1 = dbih[2*tid+1] + g_gic[b*GG+2*tid+1];
    #pragma unroll 8
    for(int k=0;k<64;k++){
      float2 w = g_wiT2[k*192 + tid];
      float x = embs[k];
      a0 += w.x*x; a1 += w.y*x;
    }
    gi[2*tid]=a0; gi[2*tid+1]=a1;
    gh[2*tid]   = dbhh[2*tid]   + g_gh[b*GG+2*tid];
    gh[2*tid+1] = dbhh[2*tid+1] + g_gh[b*GG+2*tid+1];
  }
  __syncthreads();
  if(tid < 128){
    float rr = sig_acc(gi[tid]     + gh[tid]);
    float zz = sig_acc(gi[128+tid] + gh[128+tid]);
    float nn = tanhf (gi[256+tid] + rr*gh[256+tid]);
    float hv = (1.0f-zz)*nn + zz*hold[tid];
    g_h[b*HH + tid] = hv;
    hnew[tid] = hv;
  }
  __syncthreads();
  if(tid < 128){
    float f0, f1;
    if(tid < 64){ f0 = hnew[2*tid]; f1 = hnew[2*tid+1]; }
    else        { f0 = ctxs[2*tid-128]; f1 = ctxs[2*tid-127]; }
    uint32_t h,m;
    split2h(make_float2(f0,f1), h, m);
    g_xh[b*128+tid]=h; g_xm[b*128+tid]=m;
  }
}

// ---------------- fused: attention(t+1) || logits(t) tile pool (NT2=32) ----------------
#define BSTR 528u
#define SPL (32u*BSTR)
#define BUFB (2u*SPL)
#define LOG_DYN (2*BUFB)        // 67584
__global__ void __launch_bounds__(256,2) k_fused(const float* __restrict__ attnW,
      const float* __restrict__ attnv, const float* __restrict__ outb,
      float* __restrict__ out, int t, int do_att, int slot){
  extern __shared__ char dyn[];
  __shared__ SAtt satt;
  __shared__ int s_tile;
  int cta = blockIdx.x, tid = threadIdx.x;
  int lane = tid&31, warp = tid>>5;
  uint32_t sb = s2u(dyn);

  // ---- prefetch first (static) weight tile ----
  int cur = cta;                           // tile id < GRID < NTILES
  {
    const char* sH = (const char*)g_Wh + (size_t)cur*NT2*512;
    const char* sM = (const char*)g_Wm + (size_t)cur*NT2*512;
    #pragma unroll
    for(int j=0;j<4;j++){
      int idx = tid + j*256;               // 0..1023
      uint32_t off = (uint32_t)(idx>>5)*BSTR + (uint32_t)(idx&31)*16u;
      cpasync16(sb + off,       sH + (size_t)idx*16);
      cpasync16(sb + SPL + off, sM + (size_t)idx*16);
    }
    asm volatile("cp.async.commit_group;" ::: "memory");
  }

  // ---- attention for next step (CTAs 0..127) ----
  if(do_att && cta < 128) att_work(&satt, cta, attnW, attnv);

  // ---- logits tile pool ----
  int r = lane>>2, tig = lane&3;
  int b0 = warp*16 + r, b1 = b0 + 8;
  uint32_t lrow = (uint32_t)(lane&7) + (uint32_t)((lane>>4)<<3);
  uint32_t lkadd = (uint32_t)(((lane>>3)&1)<<4);
  float* outRow = out + (size_t)t*BB*VV;
  const float INVS = 1.0f/2048.0f;
  int* tctr = &g_tctr[slot];

  int bufi = 0;
  while(cur < NTILES){
    __syncthreads();
    if(tid==0) s_tile = atomicAdd(tctr, 1);
    __syncthreads();
    int nxt = s_tile;
    uint32_t curb = sb + (bufi ? BUFB : 0u);
    uint32_t nxtb = sb + (bufi ? 0u : BUFB);
    if(nxt < NTILES){
      const char* sH = (const char*)g_Wh + (size_t)nxt*NT2*512;
      const char* sM = (const char*)g_Wm + (size_t)nxt*NT2*512;
      #pragma unroll
      for(int j=0;j<4;j++){
        int idx = tid + j*256;             // 0..1023
        uint32_t off = (uint32_t)(idx>>5)*BSTR + (uint32_t)(idx&31)*16u;
        cpasync16(nxtb + off,       sH + (size_t)idx*16);
        cpasync16(nxtb + SPL + off, sM + (size_t)idx*16);
      }
    }
    asm volatile("cp.async.commit_group;" ::: "memory");
    asm volatile("cp.async.wait_group 1;" ::: "memory");
    __syncthreads();

    int v0 = cur*NT2;
    float c1[4][4], c2[4][4];
    #pragma unroll
    for(int i=0;i<4;i++){
      c1[i][0]=0.f;c1[i][1]=0.f;c1[i][2]=0.f;c1[i][3]=0.f;
      c2[i][0]=0.f;c2[i][1]=0.f;c2[i][2]=0.f;c2[i][3]=0.f;
    }
    #pragma unroll
    for(int kc=0;kc<2;kc++){
      uint32_t ah[8][4], am[8][4];
      int base0 = b0*128 + kc*64 + tig;
      int base1 = b1*128 + kc*64 + tig;
      #pragma unroll
      for(int ks=0;ks<8;ks++){
        int i0 = base0 + ks*8, i1 = base1 + ks*8;
        ah[ks][0]=g_xh[i0]; ah[ks][1]=g_xh[i1]; ah[ks][2]=g_xh[i0+4]; ah[ks][3]=g_xh[i1+4];
        am[ks][0]=g_xm[i0]; am[ks][1]=g_xm[i1]; am[ks][2]=g_xm[i0+4]; am[ks][3]=g_xm[i1+4];
      }
      #pragma unroll
      for(int ks=0;ks<8;ks++){
        uint32_t kb = (uint32_t)(kc*128 + ks*16)*2u;
        #pragma unroll
        for(int nsp=0;nsp<2;nsp++){
          uint32_t rowoff = ((uint32_t)nsp*16u + lrow)*BSTR + kb + lkadd;
          uint32_t h0a,h1a,h0b,h1b, m0a,m1a,m0b,m1b;
          LDSM4(h0a,h1a,h0b,h1b, curb + rowoff);
          LDSM4(m0a,m1a,m0b,m1b, curb + SPL + rowoff);
          MMA(c1[2*nsp],   ah[ks], h0a,h1a);
          MMA(c2[2*nsp],   ah[ks], m0a,m1a);
          MMA(c2[2*nsp],   am[ks], h0a,h1a);
          MMA(c1[2*nsp+1], ah[ks], h0b,h1b);
          MMA(c2[2*nsp+1], ah[ks], m0b,m1b);
          MMA(c2[2*nsp+1], am[ks], h0b,h1b);
        }
      }
    }
    // epilogue
    float bv0=-3.4e38f, bv1=-3.4e38f; int bi0=0x7fffffff, bi1=0x7fffffff;
    #pragma unroll
    for(int ns=0;ns<4;ns++){
      int n = ns*8 + tig*2;
      float2 bb = *(const float2*)(outb + v0 + n);
      float f0 = c1[ns][0] + c2[ns][0]*INVS + bb.x;
      float f1 = c1[ns][1] + c2[ns][1]*INVS + bb.y;
      float f2 = c1[ns][2] + c2[ns][2]*INVS + bb.x;
      float f3 = c1[ns][3] + c2[ns][3]*INVS + bb.y;
      if(f0>bv0){bv0=f0;bi0=v0+n;}
      if(f1>bv0){bv0=f1;bi0=v0+n+1;}
      if(f2>bv1){bv1=f2;bi1=v0+n;}
      if(f3>bv1){bv1=f3;bi1=v0+n+1;}
      *(float2*)(outRow + (size_t)b0*VV + v0 + n) = make_float2(f0,f1);
      *(float2*)(outRow + (size_t)b1*VV + v0 + n) = make_float2(f2,f3);
    }
    #pragma unroll
    for(int o=1;o<4;o<<=1){
      float ov0=__shfl_xor_sync(0xffffffffu,bv0,o); int oi0=__shfl_xor_sync(0xffffffffu,bi0,o);
      float ov1=__shfl_xor_sync(0xffffffffu,bv1,o); int oi1=__shfl_xor_sync(0xffffffffu,bi1,o);
      if(ov0>bv0||(ov0==bv0&&oi0<bi0)){bv0=ov0;bi0=oi0;}
      if(ov1>bv1||(ov1==bv1&&oi1<bi1)){bv1=ov1;bi1=oi1;}
    }
    if(tig==0){
      g_pval[(size_t)b0*1024 + cur]=bv0; g_pidx[(size_t)b0*1024 + cur]=bi0;
      g_pval[(size_t)b1*1024 + cur]=bv1; g_pidx[(size_t)b1*1024 + cur]=bi1;
    }
    cur = nxt;
    bufi ^= 1;
  }
}

// ---------------- launch ----------------
extern "C" void kernel_launch(void* const* d_in, const int* in_sizes, int n_in,
                              void* d_out, int out_size) {
  const int*   seq     = (const int*)  d_in[0];
  const float* emb     = (const float*)d_in[2];
  const float* encWih  = (const float*)d_in[3];
  const float* encWhh  = (const float*)d_in[4];
  const float* encbih  = (const float*)d_in[5];
  const float* encbhh  = (const float*)d_in[6];
  const float* attnW   = (const float*)d_in[7];
  const float* attnb   = (const float*)d_in[8];
  const float* attnv   = (const float*)d_in[9];
  const float* dWih    = (const float*)d_in[10];
  const float* dWhh    = (const float*)d_in[11];
  const float* dbih    = (const float*)d_in[12];
  const float* dbhh    = (const float*)d_in[13];
  const float* outW    = (const float*)d_in[14];
  const float* outb    = (const float*)d_in[15];
  float* out = (float*)d_out;

  const int ENC_SMEM = (12288 + 128 + 384 + 384) * 4;
  cudaFuncSetAttribute(k_encrec, cudaFuncAttributeMaxDynamicSharedMemorySize, ENC_SMEM);
  cudaFuncSetAttribute(k_fused,  cudaFuncAttributeMaxDynamicSharedMemorySize, LOG_DYN);

  // setup (no probe this round)
  k_wsplit<<<8000, 256>>>(outW);
  k_wtrans<<<240, 256>>>(dWih, dWhh);
  k_giall<<<512, 384>>>(seq, emb, encWih, encbih);   // resets g_tctr
  k_encrec<<<128, 384, ENC_SMEM>>>(encWhh, encbhh);
  k_encproj<<<512, 256>>>(attnW, attnb);
  k_eo16<<<16384, 256>>>();
  k_trP2<<<dim3(32,4,128), dim3(32,8)>>>();
  k_att0<<<128, 256>>>(attnW, attnv);   // attention state for step 0

  // decode: 2 kernels per step; attention(t+1) overlaps logits(t)
  for(int t=0; t<TT; t++){
    k_gru<<<128, 256>>>(seq, emb, dbih, dbhh, t);
    k_fused<<<GRID, 256, LOG_DYN>>>(attnW, attnv, outb, out, t, (t < TT-1) ? 1 : 0, t);
  }
}

// round 17
// speedup vs baseline: 1.3255x; 1.1140x over previous
#include <cuda_runtime.h>
#include <cuda_bf16.h>
#include <cuda_fp16.h>
#include <math.h>
#include <stdint.h>

#define VV 32000
#define EE 64
#define HH 128
#define SS 1024
#define BB 128
#define TT 64
#define GG 384
#define NT2 32
#define NTILES 1000        // VV / NT2
#define GRID 256

// ---------------- device scratch ----------------
__device__ float g_gi[(size_t)SS*BB*GG];
__device__ float g_eoT[(size_t)BB*SS*HH];     // enc_out [b][s][h] fp32
__device__ __half g_eo16[(size_t)BB*SS*HH];   // enc_out [b][s][h] fp16 (context reads)
__device__ float g_epBS[(size_t)BB*SS*HH];    // enc_proj [b][s][h] fp32
__device__ __half g_epT[(size_t)BB*HH*SS];    // enc_proj [b][h][s] fp16 (score reads)
__device__ __half g_Wh[(size_t)VV*256];       // fp16 high split [v][k]
__device__ __half g_Wm[(size_t)VV*256];       // fp16 residual * 2048
__device__ float2 g_wiT2[192*192];            // [k][jpair] of dec_Wih
__device__ float2 g_whT2[128*192];            // [k][jpair] of dec_Whh
__device__ float g_h[BB*HH];
__device__ float g_ctx[BB*HH];                // ctx for current step
__device__ float g_gh[BB*GG];                 // Whh . h (no bias)
__device__ float g_gic[BB*GG];                // Wih[:,64:] . ctx (no bias)
__device__ uint4 g_xfA[8*2*8*32];             // x hi fragments [w][kc][ks][lane] (4 regs)
__device__ uint4 g_xfM[8*2*8*32];             // x residual*2048 fragments
__device__ float g_pval[(size_t)BB*1024];
__device__ int   g_pidx[(size_t)BB*1024];
__device__ int   g_tctr[TT+1];                // per-step tile counters

__device__ __forceinline__ float sig_acc(float x){ return 1.0f/(1.0f + expf(-x)); }
// 1-MUFU tanh: exp via MUFU, reciprocal via bit-trick + 3 Newton iters (~1e-8 rel err)
__device__ __forceinline__ float tanh_fast(float x){
  x = fminf(fmaxf(x, -10.0f), 10.0f);
  float e = __expf(2.0f*x);
  float y = 1.0f + e;
  float u = __uint_as_float(0x7EF311C3u - __float_as_uint(y));
  u = u*(2.0f - y*u);
  u = u*(2.0f - y*u);
  u = u*(2.0f - y*u);
  return 1.0f - 2.0f*u;
}

// ---------------- helpers ----------------
__device__ __forceinline__ uint32_t s2u(const void* p){
  uint32_t a;
  asm("{ .reg .u64 t; cvta.to.shared.u64 t, %1; cvt.u32.u64 %0, t; }" : "=r"(a) : "l"(p));
  return a;
}
__device__ __forceinline__ uint32_t pack_h2(__half lo, __half hi){
  __half2 t = __halves2half2(lo, hi);
  return *(uint32_t*)&t;
}
__device__ __forceinline__ void split2h(float2 f, uint32_t& h, uint32_t& m){
  __half h0=__float2half_rn(f.x), h1=__float2half_rn(f.y);
  float r0=(f.x-__half2float(h0))*2048.0f, r1=(f.y-__half2float(h1))*2048.0f;
  h = pack_h2(h0,h1);
  m = pack_h2(__float2half_rn(r0), __float2half_rn(r1));
}
__device__ __forceinline__ void cpasync16(uint32_t saddr, const void* gaddr){
  asm volatile("cp.async.cg.shared.global [%0], [%1], 16;" :: "r"(saddr), "l"(gaddr) : "memory");
}

#define MMA(cc, aa, bb0, bb1) \
  asm volatile("mma.sync.aligned.m16n8k16.row.col.f32.f16.f16.f32 " \
    "{%0,%1,%2,%3}, {%4,%5,%6,%7}, {%8,%9}, {%0,%1,%2,%3};" \
    : "+f"(cc[0]),"+f"(cc[1]),"+f"(cc[2]),"+f"(cc[3]) \
    : "r"(aa[0]),"r"(aa[1]),"r"(aa[2]),"r"(aa[3]), "r"(bb0),"r"(bb1))

#define LDSM4(r0,r1,r2,r3,addr) \
  asm volatile("ldmatrix.sync.aligned.m8n8.x4.shared.b16 {%0,%1,%2,%3}, [%4];" \
    : "=r"(r0),"=r"(r1),"=r"(r2),"=r"(r3) : "r"(addr))

// ---------------- setup: split out_W into 2 fp16 levels ----------------
__global__ void k_wsplit(const float* __restrict__ outW){
  size_t i4 = (size_t)blockIdx.x*256 + threadIdx.x;
  float4 w = ((const float4*)outW)[i4];
  uint2 uh, um;
  split2h(make_float2(w.x,w.y), uh.x, um.x);
  split2h(make_float2(w.z,w.w), uh.y, um.y);
  ((uint2*)g_Wh)[i4] = uh;
  ((uint2*)g_Wm)[i4] = um;
}

// ---------------- setup: transpose decoder GRU weights ----------------
__global__ void k_wtrans(const float* __restrict__ dWih, const float* __restrict__ dWhh){
  int idx = blockIdx.x*256 + threadIdx.x;
  if(idx < 192*192){
    int k = idx/192, j = idx%192;
    g_wiT2[idx] = make_float2(dWih[(size_t)(2*j)*192+k], dWih[(size_t)(2*j+1)*192+k]);
  } else {
    int i2 = idx - 192*192;
    if(i2 < 128*192){
      int k = i2/192, j = i2%192;
      g_whT2[i2] = make_float2(dWhh[(size_t)(2*j)*128+k], dWhh[(size_t)(2*j+1)*128+k]);
    }
  }
}

// ---------------- encoder input projection (also resets tile counters) ----------------
__global__ void __launch_bounds__(384,2) k_giall(const int* __restrict__ seq,
      const float* __restrict__ emb, const float* __restrict__ Wih,
      const float* __restrict__ bih){
  if(blockIdx.x==0 && threadIdx.x < TT+1) g_tctr[threadIdx.x] = GRID;
  int g = threadIdx.x;
  float w[64];
  const float4* wp = (const float4*)(Wih + (size_t)g*64);
  #pragma unroll
  for(int i=0;i<16;i++){ float4 q=wp[i]; w[4*i]=q.x; w[4*i+1]=q.y; w[4*i+2]=q.z; w[4*i+3]=q.w; }
  float bias = bih[g];
  __shared__ float xs[2][64];
  const int ROWS = (SS*BB)/512;
  size_t base = (size_t)blockIdx.x * ROWS;
  if(g<64){ int tok0 = seq[base]; xs[0][g] = emb[(size_t)tok0*EE + g]; }
  __syncthreads();
  for(int r=0;r<ROWS;r++){
    int cur=r&1, nxt=cur^1;
    if(r+1<ROWS && g<64){
      int tok2 = seq[base+r+1];
      xs[nxt][g] = emb[(size_t)tok2*EE + g];
    }
    float a0=0,a1=0,a2=0,a3=0;
    #pragma unroll
    for(int k=0;k<64;k+=4){
      a0 += w[k]*xs[cur][k];     a1 += w[k+1]*xs[cur][k+1];
      a2 += w[k+2]*xs[cur][k+2]; a3 += w[k+3]*xs[cur][k+3];
    }
    g_gi[(base+r)*GG + g] = (a0+a1)+(a2+a3) + bias;
    __syncthreads();
  }
}

// ---------------- encoder recurrence ----------------
__global__ void __launch_bounds__(384,1) k_encrec(const float* __restrict__ Whh,
      const float* __restrict__ bhh){
  extern __shared__ float sm[];
  float* whh_s = sm;
  float* hs    = sm + 12288;
  float* ghs   = hs + 128;
  float* gis   = ghs + 384;
  int b = blockIdx.x;
  int g = threadIdx.x;
  float w[96];
  {
    const float4* wlo = (const float4*)(Whh + (size_t)g*128);
    #pragma unroll
    for(int i=0;i<24;i++){ float4 q=wlo[i]; w[4*i]=q.x; w[4*i+1]=q.y; w[4*i+2]=q.z; w[4*i+3]=q.w; }
    const float4* whi = (const float4*)(Whh + (size_t)g*128 + 96);
    #pragma unroll
    for(int i=0;i<8;i++) ((float4*)whh_s)[i*384 + g] = whi[i];
  }
  float bias = bhh[g];
  if(g<128) hs[g] = 0.0f;
  __syncthreads();

  float giv = g_gi[(size_t)b*GG + g];
  for(int s=0;s<SS;s++){
    float gi_next = 0.0f;
    if(s+1<SS) gi_next = g_gi[((size_t)(s+1)*BB + b)*GG + g];
    gis[g] = giv;
    float a0=0,a1=0,a2=0,a3=0;
    #pragma unroll
    for(int i=0;i<24;i++){
      float4 hv = ((float4*)hs)[i];
      a0 += w[4*i]*hv.x;   a1 += w[4*i+1]*hv.y;
      a2 += w[4*i+2]*hv.z; a3 += w[4*i+3]*hv.w;
    }
    #pragma unroll
    for(int i=0;i<8;i++){
      float4 wv = ((float4*)whh_s)[i*384 + g];
      float4 hv = ((float4*)hs)[24 + i];
      a0 += wv.x*hv.x; a1 += wv.y*hv.y; a2 += wv.z*hv.z; a3 += wv.w*hv.w;
    }
    ghs[g] = (a0+a1)+(a2+a3) + bias;
    __syncthreads();
    if(g<128){
      float rr = sig_acc(gis[g]       + ghs[g]);
      float zz = sig_acc(gis[128+g]   + ghs[128+g]);
      float nn = tanhf (gis[256+g] + rr*ghs[256+g]);
      float hn = (1.0f-zz)*nn + zz*hs[g];
      g_eoT[((size_t)b*SS + s)*HH + g] = hn;
      hs[g] = hn;
    }
    __syncthreads();
    giv = gi_next;
  }
  if(g<128) g_h[b*HH + g] = hs[g];
}

// ---------------- enc_proj ----------------
__global__ void __launch_bounds__(256,2) k_encproj(const float* __restrict__ attnW,
                                                   const float* __restrict__ attnb){
  int t = threadIdx.x;
  int j = t & 127, half = t >> 7;
  float w[64];
  const float4* wp = (const float4*)(attnW + (size_t)j*256 + 128 + half*64);
  #pragma unroll
  for(int i=0;i<16;i++){ float4 q=wp[i]; w[4*i]=q.x; w[4*i+1]=q.y; w[4*i+2]=q.z; w[4*i+3]=q.w; }
  float bias = attnb[j];
  __shared__ float xs[2][128];
  __shared__ float part[2][128];
  const int ROWS = (SS*BB)/512;
  size_t base = (size_t)blockIdx.x * ROWS;
  if(t<128) xs[0][t] = g_eoT[base*HH + t];
  __syncthreads();
  for(int r=0;r<ROWS;r++){
    int cur=r&1, nxt=cur^1;
    if(r+1<ROWS && t<128) xs[nxt][t] = g_eoT[(base+r+1)*HH + t];
    float a0=0,a1=0,a2=0,a3=0;
    const float* xp = &xs[cur][half*64];
    #pragma unroll
    for(int k=0;k<64;k+=4){
      a0+=w[k]*xp[k]; a1+=w[k+1]*xp[k+1]; a2+=w[k+2]*xp[k+2]; a3+=w[k+3]*xp[k+3];
    }
    part[half][j] = (a0+a1)+(a2+a3);
    __syncthreads();
    if(!half) g_epBS[(base+r)*HH + j] = part[0][j] + part[1][j] + bias;
    __syncthreads();
  }
}

// ---------------- convert enc_out to fp16 [b][s][h] ----------------
__global__ void k_eo16(){
  size_t i4 = (size_t)blockIdx.x*256 + threadIdx.x;
  float4 v = ((const float4*)g_eoT)[i4];
  uint2 o;
  o.x = pack_h2(__float2half_rn(v.x), __float2half_rn(v.y));
  o.y = pack_h2(__float2half_rn(v.z), __float2half_rn(v.w));
  ((uint2*)g_eo16)[i4] = o;
}

// ---------------- per-b transpose enc_proj -> fp16 [b][h][s] ----------------
__global__ void k_trP2(){
  __shared__ float tile[32][33];
  int b = blockIdx.z;
  int s0 = blockIdx.x*32, h0 = blockIdx.y*32;
  int tx = threadIdx.x, ty = threadIdx.y;
  #pragma unroll
  for(int i=0;i<32;i+=8)
    tile[ty+i][tx] = g_epBS[((size_t)b*SS + s0+ty+i)*HH + h0+tx];
  __syncthreads();
  #pragma unroll
  for(int i=0;i<32;i+=8)
    g_epT[((size_t)b*HH + h0+ty+i)*SS + s0+tx] = __float2half_rn(tile[tx][ty+i]);
}

// ---------------- attention (fp16 streams, 1-MUFU tanh) ----------------
struct SAtt {
  float hs[128], hp[128], part[128], vsd[128];
  float ws[1024];
  float red[40];
  float4 cbuf[8][32];
};

__device__ void att_work(SAtt* S, int b, const float* __restrict__ attnW,
                         const float* __restrict__ attnv){
  int tid = threadIdx.x, lane = tid&31, warp = tid>>5;
  if(tid<128){ S->hs[tid] = g_h[b*HH + tid]; S->vsd[tid] = attnv[tid]; }
  __syncthreads();
  // hp = h @ attn_W[:, :128].T
  {
    int j = tid & 127, half = tid >> 7;
    const float4* wr = (const float4*)(attnW + (size_t)j*256 + half*64);
    const float* hb = &S->hs[half*64];
    float a = 0.0f;
    #pragma unroll
    for(int i=0;i<16;i++){
      float4 q = wr[i];
      a += q.x*hb[4*i] + q.y*hb[4*i+1] + q.z*hb[4*i+2] + q.w*hb[4*i+3];
    }
    if(half) S->part[j] = a;
    __syncthreads();
    if(!half) S->hp[j] = a + S->part[j];
    __syncthreads();
  }
  // scores: fp16 half2 loads
  {
    const __half2* base = (const __half2*)(g_epT + (size_t)b*HH*SS);
    float a0=0,a1=0,a2=0,a3=0;
    #pragma unroll 4
    for(int h=0;h<128;h++){
      float hpv = S->hp[h], vv = S->vsd[h];
      const __half2* p = base + h*(SS/2) + tid;
      __half2 q0 = p[0];
      __half2 q1 = p[256];
      float e0 = __low2float(q0), e1 = __high2float(q0);
      float e2 = __low2float(q1), e3 = __high2float(q1);
      a0 += tanh_fast(e0+hpv)*vv;
      a1 += tanh_fast(e1+hpv)*vv;
      a2 += tanh_fast(e2+hpv)*vv;
      a3 += tanh_fast(e3+hpv)*vv;
    }
    S->ws[2*tid]=a0; S->ws[2*tid+1]=a1;
    S->ws[512+2*tid]=a2; S->ws[512+2*tid+1]=a3;
  }
  __syncthreads();
  // softmax
  {
    float4 sc = ((float4*)S->ws)[tid];
    float m = fmaxf(fmaxf(sc.x,sc.y), fmaxf(sc.z,sc.w));
    #pragma unroll
    for(int o=16;o;o>>=1) m = fmaxf(m, __shfl_xor_sync(0xffffffffu,m,o));
    if(lane==0) S->red[warp] = m;
    __syncthreads();
    if(tid==0){ float mm=S->red[0]; for(int i=1;i<8;i++) mm=fmaxf(mm,S->red[i]); S->red[8]=mm; }
    __syncthreads();
    float M = S->red[8];
    float4 e;
    e.x=expf(sc.x-M); e.y=expf(sc.y-M); e.z=expf(sc.z-M); e.w=expf(sc.w-M);
    ((float4*)S->ws)[tid] = e;
    float ssum = (e.x+e.y)+(e.z+e.w);
    #pragma unroll
    for(int o=16;o;o>>=1) ssum += __shfl_xor_sync(0xffffffffu, ssum, o);
    if(lane==0) S->red[16+warp] = ssum;
    __syncthreads();
    if(tid==0){ float s2=0; for(int i=0;i<8;i++) s2+=S->red[16+i]; S->red[24]=s2; }
    __syncthreads();
  }
  float inv = 1.0f / S->red[24];
  // context: fp16 eo reads
  {
    int hq = tid&31, sg = tid>>5;
    const uint2* base = (const uint2*)(g_eo16 + (size_t)b*SS*HH);
    float4 acc = make_float4(0,0,0,0);
    #pragma unroll 4
    for(int i=0;i<128;i++){
      int s = sg + (i<<3);
      float wg = S->ws[s];
      uint2 raw = base[s*32 + hq];
      __half2 ab = *(__half2*)&raw.x;
      __half2 cd = *(__half2*)&raw.y;
      acc.x += wg*__low2float(ab); acc.y += wg*__high2float(ab);
      acc.z += wg*__low2float(cd); acc.w += wg*__high2float(cd);
    }
    S->cbuf[sg][hq] = acc;
    __syncthreads();
    if(tid<32){
      float4 tot = S->cbuf[0][tid];
      #pragma unroll
      for(int g2=1;g2<8;g2++){
        float4 c = S->cbuf[g2][tid];
        tot.x+=c.x; tot.y+=c.y; tot.z+=c.z; tot.w+=c.w;
      }
      tot.x*=inv; tot.y*=inv; tot.z*=inv; tot.w*=inv;
      int h0 = tid*4;
      S->part[h0]=tot.x; S->part[h0+1]=tot.y; S->part[h0+2]=tot.z; S->part[h0+3]=tot.w;
      g_ctx[b*HH+h0]=tot.x; g_ctx[b*HH+h0+1]=tot.y;
      g_ctx[b*HH+h0+2]=tot.z; g_ctx[b*HH+h0+3]=tot.w;
    }
  }
  __syncthreads();
  // gh = Whh.h ; gic = Wih[:,64:].ctx (no biases)
  if(tid < 192){
    float g0=0,g1=0,c0=0,c1=0;
    #pragma unroll 4
    for(int k=0;k<128;k++){
      float2 wh2 = g_whT2[k*192 + tid];
      float2 wi2 = g_wiT2[(64+k)*192 + tid];
      float hv = S->hs[k], cv = S->part[k];
      g0 += wh2.x*hv; g1 += wh2.y*hv;
      c0 += wi2.x*cv; c1 += wi2.y*cv;
    }
    g_gh[b*GG+2*tid]=g0;  g_gh[b*GG+2*tid+1]=g1;
    g_gic[b*GG+2*tid]=c0; g_gic[b*GG+2*tid+1]=c1;
  }
}

// ---------------- setup attention (step 0) ----------------
__global__ void __launch_bounds__(256,1) k_att0(const float* __restrict__ attnW,
                                                const float* __restrict__ attnv){
  __shared__ SAtt satt;
  att_work(&satt, blockIdx.x, attnW, attnv);
}

// ---------------- decoder GRU (serial-path kernel) ----------------
__global__ void __launch_bounds__(256,4) k_gru(const int* __restrict__ seq,
      const float* __restrict__ emb, const float* __restrict__ dbih,
      const float* __restrict__ dbhh, int t){
  __shared__ float embs[64], gi[384], gh[384], hold[128], hnew[128], ctxs[128];
  __shared__ float sv[8]; __shared__ int si8[8]; __shared__ int stok;
  int b = blockIdx.x, tid = threadIdx.x;
  int lane = tid&31, warp = tid>>5;
  if(t == 0){
    if(tid==0) stok = seq[b];
  } else {
    float v=-3.4e38f; int ix=0x7fffffff;
    for(int idx=tid; idx<NTILES; idx+=256){
      float pv = g_pval[(size_t)b*1024+idx]; int pi = g_pidx[(size_t)b*1024+idx];
      if(pv>v || (pv==v && pi<ix)){ v=pv; ix=pi; }
    }
    #pragma unroll
    for(int o=16;o;o>>=1){
      float ov=__shfl_xor_sync(0xffffffffu,v,o); int oi=__shfl_xor_sync(0xffffffffu,ix,o);
      if(ov>v || (ov==v && oi<ix)){ v=ov; ix=oi; }
    }
    if(lane==0){ sv[warp]=v; si8[warp]=ix; }
    __syncthreads();
    if(tid==0){
      float bv=sv[0]; int bx=si8[0];
      for(int i=1;i<8;i++) if(sv[i]>bv || (sv[i]==bv && si8[i]<bx)){ bv=sv[i]; bx=si8[i]; }
      stok = bx;
    }
  }
  __syncthreads();
  if(tid < 64) embs[tid] = emb[(size_t)stok*EE + tid];
  if(tid < 128){ hold[tid] = g_h[b*HH + tid]; ctxs[tid] = g_ctx[b*HH + tid]; }
  __syncthreads();
  if(tid < 192){
    float a0 = dbih[2*tid]   + g_gic[b*GG+2*tid];
    float a1 = dbih[2*tid+1] + g_gic[b*GG+2*tid+1];
    #pragma unroll 8
    for(int k=0;k<64;k++){
      float2 w = g_wiT2[k*192 + tid];
      float x = embs[k];
      a0 += w.x*x; a1 += w.y*x;
    }
    gi[2*tid]=a0; gi[2*tid+1]=a1;
    gh[2*tid]   = dbhh[2*tid]   + g_gh[b*GG+2*tid];
    gh[2*tid+1] = dbhh[2*tid+1] + g_gh[b*GG+2*tid+1];
  }
  __syncthreads();
  if(tid < 128){
    float rr = sig_acc(gi[tid]     + gh[tid]);
    float zz = sig_acc(gi[128+tid] + gh[128+tid]);
    float nn = tanhf (gi[256+tid] + rr*gh[256+tid]);
    float hv = (1.0f-zz)*nn + zz*hold[tid];
    g_h[b*HH + tid] = hv;
    hnew[tid] = hv;
  }
  __syncthreads();
  // pack x into MMA-fragment order: g_xfA/g_xfM[(w,kc,ks)][lane][reg]
  if(tid < 128){
    float f0, f1;
    if(tid < 64){ f0 = hnew[2*tid]; f1 = hnew[2*tid+1]; }
    else        { f0 = ctxs[2*tid-128]; f1 = ctxs[2*tid-127]; }
    uint32_t h,m;
    split2h(make_float2(f0,f1), h, m);
    int w = b>>4, r = b&7, rowhalf = (b>>3)&1;
    int k = tid;                       // word index 0..127
    int kc = k>>6, k6 = k&63, ks = k6>>3, w8 = k6&7;
    int tig = w8&3, base = (w8<4)?0:2;
    int reg = base + rowhalf;
    int dest = ((((w*2 + kc)*8 + ks)*32) + (r*4 + tig))*4 + reg;
    ((uint32_t*)g_xfA)[dest] = h;
    ((uint32_t*)g_xfM)[dest] = m;
  }
}

// ---------------- fused: attention(t+1) || logits(t) tile pool (NT2=32) ----------------
#define BSTR 528u
#define SPL (32u*BSTR)
#define BUFB (2u*SPL)
#define LOG_DYN (2*BUFB)        // 67584
__global__ void __launch_bounds__(256,2) k_fused(const float* __restrict__ attnW,
      const float* __restrict__ attnv, const float* __restrict__ outb,
      float* __restrict__ out, int t, int do_att, int slot){
  extern __shared__ char dyn[];
  __shared__ SAtt satt;
  __shared__ int s_tile;
  int cta = blockIdx.x, tid = threadIdx.x;
  int lane = tid&31, warp = tid>>5;
  uint32_t sb = s2u(dyn);

  // ---- prefetch first (static) weight tile ----
  int cur = cta;                           // tile id < GRID < NTILES
  {
    const char* sH = (const char*)g_Wh + (size_t)cur*NT2*512;
    const char* sM = (const char*)g_Wm + (size_t)cur*NT2*512;
    #pragma unroll
    for(int j=0;j<4;j++){
      int idx = tid + j*256;               // 0..1023
      uint32_t off = (uint32_t)(idx>>5)*BSTR + (uint32_t)(idx&31)*16u;
      cpasync16(sb + off,       sH + (size_t)idx*16);
      cpasync16(sb + SPL + off, sM + (size_t)idx*16);
    }
    asm volatile("cp.async.commit_group;" ::: "memory");
  }

  // ---- attention for next step (CTAs 0..127) ----
  if(do_att && cta < 128) att_work(&satt, cta, attnW, attnv);

  // ---- logits tile pool ----
  int r = lane>>2, tig = lane&3;
  int b0 = warp*16 + r, b1 = b0 + 8;
  uint32_t lrow = (uint32_t)(lane&7) + (uint32_t)((lane>>4)<<3);
  uint32_t lkadd = (uint32_t)(((lane>>3)&1)<<4);
  float* outRow = out + (size_t)t*BB*VV;
  const float INVS = 1.0f/2048.0f;
  int* tctr = &g_tctr[slot];

  int bufi = 0;
  while(cur < NTILES){
    __syncthreads();
    if(tid==0) s_tile = atomicAdd(tctr, 1);
    __syncthreads();
    int nxt = s_tile;
    uint32_t curb = sb + (bufi ? BUFB : 0u);
    uint32_t nxtb = sb + (bufi ? 0u : BUFB);
    if(nxt < NTILES){
      const char* sH = (const char*)g_Wh + (size_t)nxt*NT2*512;
      const char* sM = (const char*)g_Wm + (size_t)nxt*NT2*512;
      #pragma unroll
      for(int j=0;j<4;j++){
        int idx = tid + j*256;             // 0..1023
        uint32_t off = (uint32_t)(idx>>5)*BSTR + (uint32_t)(idx&31)*16u;
        cpasync16(nxtb + off,       sH + (size_t)idx*16);
        cpasync16(nxtb + SPL + off, sM + (size_t)idx*16);
      }
    }
    asm volatile("cp.async.commit_group;" ::: "memory");
    asm volatile("cp.async.wait_group 1;" ::: "memory");
    __syncthreads();

    int v0 = cur*NT2;
    float c1[4][4], c2[4][4];
    #pragma unroll
    for(int i=0;i<4;i++){
      c1[i][0]=0.f;c1[i][1]=0.f;c1[i][2]=0.f;c1[i][3]=0.f;
      c2[i][0]=0.f;c2[i][1]=0.f;c2[i][2]=0.f;c2[i][3]=0.f;
    }
    #pragma unroll
    for(int kc=0;kc<2;kc++){
      uint32_t ah[8][4], am[8][4];
      #pragma unroll
      for(int ks=0;ks<8;ks++){
        int fi = ((warp*2 + kc)*8 + ks)*32 + lane;
        uint4 a4 = g_xfA[fi];
        uint4 m4 = g_xfM[fi];
        ah[ks][0]=a4.x; ah[ks][1]=a4.y; ah[ks][2]=a4.z; ah[ks][3]=a4.w;
        am[ks][0]=m4.x; am[ks][1]=m4.y; am[ks][2]=m4.z; am[ks][3]=m4.w;
      }
      #pragma unroll
      for(int ks=0;ks<8;ks++){
        uint32_t kb = (uint32_t)(kc*128 + ks*16)*2u;
        #pragma unroll
        for(int nsp=0;nsp<2;nsp++){
          uint32_t rowoff = ((uint32_t)nsp*16u + lrow)*BSTR + kb + lkadd;
          uint32_t h0a,h1a,h0b,h1b, m0a,m1a,m0b,m1b;
          LDSM4(h0a,h1a,h0b,h1b, curb + rowoff);
          LDSM4(m0a,m1a,m0b,m1b, curb + SPL + rowoff);
          MMA(c1[2*nsp],   ah[ks], h0a,h1a);
          MMA(c2[2*nsp],   ah[ks], m0a,m1a);
          MMA(c2[2*nsp],   am[ks], h0a,h1a);
          MMA(c1[2*nsp+1], ah[ks], h0b,h1b);
          MMA(c2[2*nsp+1], ah[ks], m0b,m1b);
          MMA(c2[2*nsp+1], am[ks], h0b,h1b);
        }
      }
    }
    // epilogue
    float bv0=-3.4e38f, bv1=-3.4e38f; int bi0=0x7fffffff, bi1=0x7fffffff;
    #pragma unroll
    for(int ns=0;ns<4;ns++){
      int n = ns*8 + tig*2;
      float2 bb = *(const float2*)(outb + v0 + n);
      float f0 = c1[ns][0] + c2[ns][0]*INVS + bb.x;
      float f1 = c1[ns][1] + c2[ns][1]*INVS + bb.y;
      float f2 = c1[ns][2] + c2[ns][2]*INVS + bb.x;
      float f3 = c1[ns][3] + c2[ns][3]*INVS + bb.y;
      if(f0>bv0){bv0=f0;bi0=v0+n;}
      if(f1>bv0){bv0=f1;bi0=v0+n+1;}
      if(f2>bv1){bv1=f2;bi1=v0+n;}
      if(f3>bv1){bv1=f3;bi1=v0+n+1;}
      *(float2*)(outRow + (size_t)b0*VV + v0 + n) = make_float2(f0,f1);
      *(float2*)(outRow + (size_t)b1*VV + v0 + n) = make_float2(f2,f3);
    }
    #pragma unroll
    for(int o=1;o<4;o<<=1){
      float ov0=__shfl_xor_sync(0xffffffffu,bv0,o); int oi0=__shfl_xor_sync(0xffffffffu,bi0,o);
      float ov1=__shfl_xor_sync(0xffffffffu,bv1,o); int oi1=__shfl_xor_sync(0xffffffffu,bi1,o);
      if(ov0>bv0||(ov0==bv0&&oi0<bi0)){bv0=ov0;bi0=oi0;}
      if(ov1>bv1||(ov1==bv1&&oi1<bi1)){bv1=ov1;bi1=oi1;}
    }
    if(tig==0){
      g_pval[(size_t)b0*1024 + cur]=bv0; g_pidx[(size_t)b0*1024 + cur]=bi0;
      g_pval[(size_t)b1*1024 + cur]=bv1; g_pidx[(size_t)b1*1024 + cur]=bi1;
    }
    cur = nxt;
    bufi ^= 1;
  }
}

// ---------------- launch ----------------
extern "C" void kernel_launch(void* const* d_in, const int* in_sizes, int n_in,
                              void* d_out, int out_size) {
  const int*   seq     = (const int*)  d_in[0];
  const float* emb     = (const float*)d_in[2];
  const float* encWih  = (const float*)d_in[3];
  const float* encWhh  = (const float*)d_in[4];
  const float* encbih  = (const float*)d_in[5];
  const float* encbhh  = (const float*)d_in[6];
  const float* attnW   = (const float*)d_in[7];
  const float* attnb   = (const float*)d_in[8];
  const float* attnv   = (const float*)d_in[9];
  const float* dWih    = (const float*)d_in[10];
  const float* dWhh    = (const float*)d_in[11];
  const float* dbih    = (const float*)d_in[12];
  const float* dbhh    = (const float*)d_in[13];
  const float* outW    = (const float*)d_in[14];
  const float* outb    = (const float*)d_in[15];
  float* out = (float*)d_out;

  const int ENC_SMEM = (12288 + 128 + 384 + 384) * 4;
  cudaFuncSetAttribute(k_encrec, cudaFuncAttributeMaxDynamicSharedMemorySize, ENC_SMEM);
  cudaFuncSetAttribute(k_fused,  cudaFuncAttributeMaxDynamicSharedMemorySize, LOG_DYN);

  // setup
  k_wsplit<<<8000, 256>>>(outW);
  k_wtrans<<<240, 256>>>(dWih, dWhh);
  k_giall<<<512, 384>>>(seq, emb, encWih, encbih);   // resets g_tctr
  k_encrec<<<128, 384, ENC_SMEM>>>(encWhh, encbhh);
  k_encproj<<<512, 256>>>(attnW, attnb);
  k_eo16<<<16384, 256>>>();
  k_trP2<<<dim3(32,4,128), dim3(32,8)>>>();
  k_att0<<<128, 256>>>(attnW, attnv);   // attention state for step 0

  // decode: 2 kernels per step; attention(t+1) overlaps logits(t)
  for(int t=0; t<TT; t++){
    k_gru<<<128, 256>>>(seq, emb, dbih, dbhh, t);
    k_fused<<<GRID, 256, LOG_DYN>>>(attnW, attnv, outb, out, t, (t < TT-1) ? 1 : 0, t);
  }
}